// round 1
// baseline (speedup 1.0000x reference)
#include <cuda_runtime.h>

// Reference math:
//   y = x @ W.T + b                      (B, OUT)
//   m = max(y, axis=1, keepdims=True)    (B, 1)
//   centered = m - mean(m, axis=1)       == 0 exactly (mean over a size-1 axis)
//   out = gelu_tanh(0)                   == 0 exactly
//
// The output is identically zero for ALL inputs. The GEMM is dead code.
// Fastest correct kernel: write 4096 zero floats.

__global__ void ModelNew_25056839205334_zero(float4* __restrict__ out, int n4) {
    int i = blockIdx.x * blockDim.x + threadIdx.x;
    if (i < n4) {
        out[i] = make_float4(0.0f, 0.0f, 0.0f, 0.0f);
    }
}

extern "C" void kernel_launch(void* const* d_in, const int* in_sizes, int n_in,
                              void* d_out, int out_size) {
    (void)d_in; (void)in_sizes; (void)n_in;
    // out_size = 4096 floats = 1024 float4 (16 KB). d_out is 256B-aligned
    // (harness cudaMalloc), so float4 stores are safe.
    int n4 = out_size / 4;
    int threads = 256;
    int blocks = (n4 + threads - 1) / threads;  // 4 blocks
    ModelNew_25056839205334_zero<<<blocks, threads>>>((float4*)d_out, n4);

    // Handle any non-multiple-of-4 tail generically (out_size=4096 -> none),
    // done inside the same launch would need scalar path; out_size is 4096
    // here so no tail exists. Guard anyway for robustness:
    int tail = out_size - n4 * 4;
    if (tail > 0) {
        // scalar tail kernel
        ModelNew_25056839205334_zero<<<1, 32>>>((float4*)((float*)d_out + n4 * 4 - 4), 1);
    }
}